// round 5
// baseline (speedup 1.0000x reference)
#include <cuda_runtime.h>

#define G_ 4
#define T_ 2048
#define E_ 8
#define D_ 1024
#define C_ 2048
#define NTOK (G_ * T_)

#define NB 148            // persistent grid: 1 block/SM guaranteed resident
#define NFILL0 40         // pure-fill blocks (start at t=0)
#define NROUTER 76        // router blocks
#define TOPK0 (NFILL0 + NROUTER)   // 116: topk blocks are 116..147
#define THREADS 1024

#define NTOT ((long long)G_ * T_ * E_ * C_)
#define N4 (2 * NTOT / 4)          // float4 count of dispatch+combine = 134217728
#define CHUNK_F4 16384             // 256 KB per chunk
#define NCHUNKS ((int)(N4 / CHUNK_F4))   // 8192 exactly

__device__ float g_probs[G_ * E_ * T_];   // expert-major probs
__device__ float g_zt[NTOK];              // per-token z partials
__device__ int   g_router_done;           // counts router blocks finished
__device__ int   g_fill_done;             // counts blocks finished filling
__device__ int   g_chunk;                 // fill work queue head

__global__ void init_kernel() {
    g_router_done = 0;
    g_fill_done = 0;
    g_chunk = 0;
}

__device__ __forceinline__ void spin_ge(volatile int* p, int target) {
    while (*p < target) __nanosleep(64);
}

// Work-stealing zero fill; returns after queue exhausted and this block counted.
__device__ __forceinline__ void do_fill(float4* __restrict__ out4) {
    const float4 z = make_float4(0.f, 0.f, 0.f, 0.f);
    __shared__ int sc;
    for (;;) {
        if (threadIdx.x == 0) sc = atomicAdd(&g_chunk, 1);
        __syncthreads();
        int c = sc;
        __syncthreads();
        if (c >= NCHUNKS) break;
        long long base = (long long)c * CHUNK_F4 + threadIdx.x;
        #pragma unroll
        for (int i = 0; i < CHUNK_F4 / THREADS; i++)
            __stcs(&out4[base + (long long)i * THREADS], z);
    }
    __threadfence();
    __syncthreads();
    if (threadIdx.x == 0) atomicAdd(&g_fill_done, 1);
}

__global__ void __launch_bounds__(THREADS, 1)
fused_kernel(const float* __restrict__ x,
             const float* __restrict__ W,
             const float* __restrict__ b,
             float* __restrict__ out) {
    __shared__ __align__(16) union {
        struct { float sW[E_ * D_]; float sb[E_]; } r;   // 32 KB (router)
        unsigned long long keys[T_];                     // 16 KB (topk sort)
        float red[THREADS];                              // z reduction
    } sm;

    float4* out4 = reinterpret_cast<float4*>(out);
    int B = blockIdx.x;

    if (B < NFILL0) {
        // ---------------- pure fill from t = 0 ----------------
        do_fill(out4);
        return;
    }

    if (B < TOPK0) {
        // ---------------- router, then fill ----------------
        for (int i = threadIdx.x; i < E_ * D_ / 4; i += THREADS)
            reinterpret_cast<float4*>(sm.r.sW)[i] =
                reinterpret_cast<const float4*>(W)[i];
        if (threadIdx.x < E_) sm.r.sb[threadIdx.x] = b[threadIdx.x];
        __syncthreads();

        int warp = threadIdx.x >> 5;
        int lane = threadIdx.x & 31;
        int wglob = (B - NFILL0) * 32 + warp;            // 0..2431

        for (int token = wglob; token < NTOK; token += NROUTER * 32) {
            int g = token / T_;
            int t = token % T_;
            const float4* x4 =
                reinterpret_cast<const float4*>(x + (long long)token * D_);

            float acc[E_];
            #pragma unroll
            for (int e = 0; e < E_; e++) acc[e] = 0.f;

            #pragma unroll
            for (int i = 0; i < D_ / (32 * 4); i++) {    // 8 iterations
                int d4 = i * 32 + lane;
                float4 xv = x4[d4];
                #pragma unroll
                for (int e = 0; e < E_; e++) {
                    float4 wv =
                        reinterpret_cast<const float4*>(sm.r.sW + e * D_)[d4];
                    acc[e] += xv.x * wv.x + xv.y * wv.y +
                              xv.z * wv.z + xv.w * wv.w;
                }
            }
            #pragma unroll
            for (int o = 16; o > 0; o >>= 1)
                #pragma unroll
                for (int e = 0; e < E_; e++)
                    acc[e] += __shfl_xor_sync(0xffffffffu, acc[e], o);

            float m = -1e30f;
            #pragma unroll
            for (int e = 0; e < E_; e++) { acc[e] += sm.r.sb[e]; m = fmaxf(m, acc[e]); }
            float ex[E_], s = 0.f;
            #pragma unroll
            for (int e = 0; e < E_; e++) { ex[e] = expf(acc[e] - m); s += ex[e]; }
            float inv = 1.f / s;
            float lse = m + logf(s);

            if (lane < E_)
                g_probs[(g * E_ + lane) * T_ + t] = ex[lane] * inv;
            if (lane == 0) {
                float zt = 0.f;
                #pragma unroll
                for (int e = 0; e < E_; e++) {
                    float ls = acc[e] - lse;
                    zt += ls * ls;
                }
                g_zt[token] = zt;
            }
        }
        __threadfence();
        __syncthreads();
        if (threadIdx.x == 0) atomicAdd(&g_router_done, 1);
        __syncthreads();     // smem union: router data no longer needed
        do_fill(out4);
        return;
    }

    // ---------------- topk: wait router -> sort -> fill -> scatter ----------------
    int ge = B - TOPK0;      // 0..31
    int e = ge & 7;
    int g = ge >> 3;

    if (threadIdx.x == 0) spin_ge(&g_router_done, NROUTER);
    __syncthreads();
    __threadfence();

    const float* p = g_probs + (long long)ge * T_;
    for (int t = threadIdx.x; t < T_; t += THREADS) {
        unsigned int pb = __float_as_uint(p[t]);   // probs > 0 -> bits monotonic
        sm.keys[t] = ((unsigned long long)pb << 32) | (unsigned int)(~t);
    }
    __syncthreads();

    for (int k = 2; k <= T_; k <<= 1) {
        for (int j = k >> 1; j > 0; j >>= 1) {
            for (int i = threadIdx.x; i < T_; i += THREADS) {
                int ixj = i ^ j;
                if (ixj > i) {
                    bool desc = ((i & k) == 0);
                    unsigned long long a = sm.keys[i], c = sm.keys[ixj];
                    if (desc ? (a < c) : (a > c)) { sm.keys[i] = c; sm.keys[ixj] = a; }
                }
            }
            __syncthreads();
        }
    }

    // keep top-cap in registers so smem can be reused during fill
    const int caps[E_] = {512, 512, 256, 256, 128, 128, 128, 128};
    int cap = caps[e];
    unsigned long long mykey = (threadIdx.x < cap) ? sm.keys[threadIdx.x] : 0ull;
    __syncthreads();

    // help finish the fill
    do_fill(out4);

    // wait for ALL blocks to finish filling, then scatter nonzeros
    if (threadIdx.x == 0) spin_ge(&g_fill_done, NB);
    __syncthreads();
    __threadfence();

    if (threadIdx.x < cap) {
        float gate = __uint_as_float((unsigned int)(mykey >> 32));
        int tok = (int)(~(unsigned int)(mykey & 0xffffffffu));
        long long off = (((long long)g * T_ + tok) * E_ + e) * C_ + threadIdx.x;
        out[off]        = 1.0f;   // dispatch_mask
        out[NTOT + off] = gate;   // combine_array
    }

    // block TOPK0 also reduces the z-loss and writes the scalar
    if (ge == 0) {
        __syncthreads();
        float acc = 0.f;
        for (int i = threadIdx.x; i < NTOK; i += THREADS)
            acc += g_zt[i];
        sm.red[threadIdx.x] = acc;
        __syncthreads();
        for (int o = THREADS / 2; o > 0; o >>= 1) {
            if (threadIdx.x < o) sm.red[threadIdx.x] += sm.red[threadIdx.x + o];
            __syncthreads();
        }
        if (threadIdx.x == 0)
            out[2 * NTOT] = sm.red[0] / (float)(G_ * T_ * E_);
    }
}

extern "C" void kernel_launch(void* const* d_in, const int* in_sizes, int n_in,
                              void* d_out, int out_size) {
    const float* x = (const float*)d_in[0];   // token_inputs [G,T,D]
    const float* W = (const float*)d_in[1];   // [E,D]
    const float* b = (const float*)d_in[2];   // [E]
    float* out = (float*)d_out;

    init_kernel<<<1, 1>>>();
    fused_kernel<<<NB, THREADS>>>(x, W, b, out);
}